// round 5
// baseline (speedup 1.0000x reference)
#include <cuda_runtime.h>

// EMA scan: sta_t = sta_{t-1} + W*(x_t - sta_{t-1}), decay a = 1-W = 0.4.
// a^32 ~ 1.8e-13 -> chunked parallel scan with 32-step warm-up is exact to fp32.

#define T_LEN   6000
#define CH      3
#define ROW_F   (T_LEN * CH)          // 18000 floats per batch row
#define WARM    32                    // warm-up steps (a^32 ~ 1.8e-13)
#define SEG     17                    // per-thread segment (51 floats stride: conflict-free banks)
#define SEGS    32                    // segments per chunk (one warp's lanes)
#define S_CHUNK (SEG * SEGS)          // 544 timesteps per chunk
#define NB      4                     // batch rows per block
#define THREADS (NB * SEGS)           // 128
#define TILE_T  (WARM + S_CHUNK)      // 576
#define TILE_F  (TILE_T * CH)         // 1728 floats per row in tile
#define N_CHUNKS ((T_LEN + S_CHUNK - 1) / S_CHUNK)  // 12
#define EMA_W   0.6f

__global__ __launch_bounds__(THREADS)
void ema_scan_kernel(const float* __restrict__ in, float* __restrict__ out) {
    __shared__ float tile[NB * TILE_F];

    const int tid   = threadIdx.x;
    const int chunk = blockIdx.x % N_CHUNKS;
    const int row0  = (blockIdx.x / N_CHUNKS) * NB;
    const int cs    = chunk * S_CHUNK;          // chunk start timestep
    const int gbase = (cs - WARM) * CH;         // float offset within row of tile start (can be <0)

    // ---- coalesced float4 load: GMEM -> SMEM tile ----
    // gbase is a multiple of 4 floats and ROW_F is a multiple of 4, so each
    // quad is entirely in-range or entirely out-of-range. OOB -> zeros, which
    // is exactly equivalent to the zero initial EMA state.
    const int totalQuads = (NB * TILE_F) / 4;
    for (int q = tid; q < totalQuads; q += THREADS) {
        int f  = q * 4;
        int r  = f / TILE_F;
        int fr = f - r * TILE_F;
        int g  = gbase + fr;
        float4 v = make_float4(0.f, 0.f, 0.f, 0.f);
        if (g >= 0 && g < ROW_F)
            v = *reinterpret_cast<const float4*>(in + (size_t)(row0 + r) * ROW_F + g);
        *reinterpret_cast<float4*>(&tile[f]) = v;
    }
    __syncthreads();

    const int s = tid & 31;    // segment index within chunk (lane)
    const int r = tid >> 5;    // batch row within block (warp)
    float* rowp = tile + r * TILE_F;

    // ---- phase 1: warm-up carry (reads only; segments overlap neighbors' data) ----
    float c0 = 0.f, c1 = 0.f, c2 = 0.f;
    {
        const float* p = rowp + (s * SEG) * CH;   // warm-up covers [SEG*s, SEG*s + WARM)
        #pragma unroll
        for (int k = 0; k < WARM; k++) {
            float x0 = p[3*k+0], x1 = p[3*k+1], x2 = p[3*k+2];
            c0 += EMA_W * (x0 - c0);
            c1 += EMA_W * (x1 - c1);
            c2 += EMA_W * (x2 - c2);
        }
    }
    __syncthreads();   // all warm-up reads complete before in-place overwrite

    // ---- phase 2: in-place segment scan (each location owned by one thread) ----
    {
        float* p = rowp + (WARM + s * SEG) * CH;
        #pragma unroll
        for (int k = 0; k < SEG; k++) {
            float x0 = p[3*k+0], x1 = p[3*k+1], x2 = p[3*k+2];
            c0 += EMA_W * (x0 - c0);
            c1 += EMA_W * (x1 - c1);
            c2 += EMA_W * (x2 - c2);
            p[3*k+0] = c0; p[3*k+1] = c1; p[3*k+2] = c2;
        }
    }
    __syncthreads();

    // ---- coalesced float4 store: SMEM chunk region -> GMEM ----
    const int outF     = S_CHUNK * CH;            // 1632 floats per row
    const int outQuads = (NB * outF) / 4;
    const int obase    = cs * CH;                 // multiple of 4 floats
    for (int q = tid; q < outQuads; q += THREADS) {
        int f  = q * 4;
        int r2 = f / outF;
        int fr = f - r2 * outF;
        int g  = obase + fr;
        if (g < ROW_F)
            *reinterpret_cast<float4*>(out + (size_t)(row0 + r2) * ROW_F + g) =
                *reinterpret_cast<const float4*>(&tile[r2 * TILE_F + WARM * CH + fr]);
    }
}

extern "C" void kernel_launch(void* const* d_in, const int* in_sizes, int n_in,
                              void* d_out, int out_size) {
    const float* wave = (const float*)d_in[0];
    float* out = (float*)d_out;
    const int B = in_sizes[0] / ROW_F;            // 4096
    const int blocks = (B / NB) * N_CHUNKS;       // 12288
    ema_scan_kernel<<<blocks, THREADS>>>(wave, out);
}

// round 9
// speedup vs baseline: 1.4800x; 1.4800x over previous
#include <cuda_runtime.h>
#include <cstdint>

// EMA scan: sta_t = sta_{t-1} + 0.6*(x_t - sta_{t-1})  ==  sta_t = 0.4*sta_{t-1} + 0.6*x_t
// decay a = 0.4, a^32 ~ 1.8e-13 -> chunked parallel scan with 32-step warm-up.

#define T_LEN   6000
#define CH      3
#define ROW_F   (T_LEN * CH)            // 18000 floats per batch row
#define WARM    32                      // warm-up steps
#define SEG     12                      // per-thread segment (36-float stride: conflict-free fl4 banks)
#define SEGS    32
#define S_CHUNK (SEG * SEGS)            // 384 timesteps per chunk
#define NB      4                       // batch rows per block
#define THREADS (NB * SEGS)             // 128
#define TILE_T  (WARM + S_CHUNK)        // 416
#define TILE_F  (TILE_T * CH)           // 1248 floats per row in tile
#define N_CHUNKS 16                     // ceil(6000/384) -> covers 6144, tail guarded
#define W_A     0.4f
#define W_W     0.6f

// one EMA step over 3 channels packed across float fields
#define STEP(X0, X1, X2)                         \
    c0 = fmaf(W_A, c0, W_W * (X0));              \
    c1 = fmaf(W_A, c1, W_W * (X1));              \
    c2 = fmaf(W_A, c2, W_W * (X2));

__global__ __launch_bounds__(THREADS)
void ema_scan_kernel(const float* __restrict__ in, float* __restrict__ out) {
    __shared__ float4 tile4[NB * TILE_F / 4];          // 19968 B
    float* tile = reinterpret_cast<float*>(tile4);

    const int tid   = threadIdx.x;
    const int chunk = blockIdx.x & (N_CHUNKS - 1);
    const int row0  = (blockIdx.x >> 4) * NB;
    const int cs    = chunk * S_CHUNK;                 // chunk start timestep
    const int gbase = cs * CH - WARM * CH;             // float offset of tile start (mult of 4)

    // ---- stage GMEM -> SMEM via cp.async (zero-fill for OOB quads) ----
    // OOB -> zeros is exactly equivalent to the zero initial EMA state.
    {
        const uint32_t sbase = (uint32_t)__cvta_generic_to_shared(tile);
        const int totalQuads = NB * TILE_F / 4;        // 1248
        #pragma unroll 4
        for (int q = tid; q < totalQuads; q += THREADS) {
            int f  = q * 4;
            int r  = f / TILE_F;
            int fr = f - r * TILE_F;
            int g  = gbase + fr;
            int gc = g < 0 ? 0 : (g > ROW_F - 4 ? ROW_F - 4 : g);   // safe clamped addr
            int sz = (g >= 0 && g < ROW_F) ? 16 : 0;                // 0 => full zero-fill
            const float* src = in + (size_t)(row0 + r) * ROW_F + gc;
            asm volatile("cp.async.cg.shared.global [%0], [%1], 16, %2;\n"
                         :: "r"(sbase + (uint32_t)q * 16), "l"(src), "r"(sz));
        }
        asm volatile("cp.async.commit_group;\n");
        asm volatile("cp.async.wait_group 0;\n");
    }
    __syncthreads();

    const int s = tid & 31;              // segment (lane)
    const int r = tid >> 5;              // batch row within block (warp)
    float* rowp = tile + r * TILE_F;

    float c0 = 0.f, c1 = 0.f, c2 = 0.f;

    // ---- phase 1: warm-up carry, float4 reads (32 steps = 24 quads) ----
    {
        const float4* wp = reinterpret_cast<const float4*>(rowp + s * (SEG * CH)); // 36-float stride
        #pragma unroll
        for (int g3 = 0; g3 < WARM / 4; g3++) {        // 8 groups of 3 quads = 4 steps each
            float4 q0 = wp[3 * g3 + 0];
            float4 q1 = wp[3 * g3 + 1];
            float4 q2 = wp[3 * g3 + 2];
            STEP(q0.x, q0.y, q0.z)
            STEP(q0.w, q1.x, q1.y)
            STEP(q1.z, q1.w, q2.x)
            STEP(q2.y, q2.z, q2.w)
        }
    }
    __syncthreads();   // all warm-up reads complete before in-place overwrite

    // ---- phase 2: in-place segment scan, float4 (12 steps = 9 quads) ----
    {
        float4* sp = reinterpret_cast<float4*>(rowp + WARM * CH + s * (SEG * CH));
        #pragma unroll
        for (int g3 = 0; g3 < SEG / 4; g3++) {
            float4 q0 = sp[3 * g3 + 0];
            float4 q1 = sp[3 * g3 + 1];
            float4 q2 = sp[3 * g3 + 2];
            STEP(q0.x, q0.y, q0.z)  q0.x = c0; q0.y = c1; q0.z = c2;
            STEP(q0.w, q1.x, q1.y)  q0.w = c0; q1.x = c1; q1.y = c2;
            STEP(q1.z, q1.w, q2.x)  q1.z = c0; q1.w = c1; q2.x = c2;
            STEP(q2.y, q2.z, q2.w)  q2.y = c0; q2.z = c1; q2.w = c2;
            sp[3 * g3 + 0] = q0;
            sp[3 * g3 + 1] = q1;
            sp[3 * g3 + 2] = q2;
        }
    }
    __syncthreads();

    // ---- coalesced float4 store: SMEM chunk region -> GMEM ----
    {
        const int outF     = S_CHUNK * CH;             // 1152 floats per row
        const int outQuads = NB * outF / 4;            // 1152
        const int obase    = cs * CH;
        #pragma unroll 4
        for (int q = tid; q < outQuads; q += THREADS) {
            int f  = q * 4;
            int r2 = f / outF;
            int fr = f - r2 * outF;
            int g  = obase + fr;
            if (g < ROW_F)
                *reinterpret_cast<float4*>(out + (size_t)(row0 + r2) * ROW_F + g) =
                    *reinterpret_cast<const float4*>(&tile[r2 * TILE_F + WARM * CH + fr]);
        }
    }
}

extern "C" void kernel_launch(void* const* d_in, const int* in_sizes, int n_in,
                              void* d_out, int out_size) {
    const float* wave = (const float*)d_in[0];
    float* out = (float*)d_out;
    const int B = in_sizes[0] / ROW_F;                 // 4096
    const int blocks = (B / NB) * N_CHUNKS;            // 16384
    ema_scan_kernel<<<blocks, THREADS>>>(wave, out);
}